// round 15
// baseline (speedup 1.0000x reference)
#include <cuda_runtime.h>
#include <cuda_bf16.h>

// Problem constants
#define Bx 4
#define Cx 3
#define Hx 224
#define Wx 224
#define Kx 196
#define Ex 768
#define HW (Hx * Wx)               // 50176
#define BK (Bx * Kx)               // 784

#define BPB 74                     // blocks per batch; 4*74 = 296 = 2 per SM
#define NBLK (Bx * BPB)            // 296
#define TA 256
#define F4_PER_BLOCK 170           // 73*170 + 134 = 12544 = HW/4
#define F4_LAST 134

#define COLS_PER_THREAD (Ex / TA)  // 3
#define MAXROWS 3                  // phase-2 rows per block

#define NREP 8                     // replicas: 6272 target rows, ~32 adds/addr
#define ROW_F4 8                   // 128 B per row -> distinct L2 lines

// Replicated pooled sums: g_pool4[rep][bk][ROW_F4]; element 0 = {c0,c1,c2,pad}.
// Zero at module load; phase 2 re-zeroes consumed rows each call. 802 KB (L2-resident).
__device__ float4 g_pool4[NREP * BK * ROW_F4];

// Per-batch sub-barriers: monotone epoch counters, 128 B apart. u64 -> no overflow.
__device__ unsigned long long g_bar[Bx * 16];

__device__ __forceinline__ void red_add_v4(float4* p, float x, float y, float z) {
    asm volatile("red.global.add.v4.f32 [%0], {%1, %2, %3, %4};"
                 :: "l"(p), "f"(x), "f"(y), "f"(z), "f"(0.0f) : "memory");
}

__device__ __forceinline__ float4 ldcg4(const float4* p) {
    float4 v;
    asm volatile("ld.global.cg.v4.f32 {%0,%1,%2,%3}, [%4];"
                 : "=f"(v.x), "=f"(v.y), "=f"(v.z), "=f"(v.w) : "l"(p));
    return v;
}

__global__ void __launch_bounds__(TA)
fused_kernel(const float* __restrict__ img,
             const int* __restrict__ seg,
             const float* __restrict__ Wmat,
             const float* __restrict__ bias,
             float* __restrict__ out) {
    const int tid = threadIdx.x;
    const int b   = blockIdx.x / BPB;
    const int j   = blockIdx.x % BPB;
    const int rep = blockIdx.x & (NREP - 1);

    // ---------------- Phase 1: pure fire-and-forget vector reductions -------
    const int nf4 = (j < BPB - 1) ? F4_PER_BLOCK : F4_LAST;
    const float* img_b = img + (size_t)b * Cx * HW;
    const int*   seg_b = seg + (size_t)b * HW;
    float4* pool_rb = g_pool4 + ((size_t)rep * BK + (size_t)b * Kx) * ROW_F4;

    if (tid < nf4) {
        const int p0 = (j * F4_PER_BLOCK + tid) * 4;

        int4   s  = *(const int4*)  (seg_b + p0);
        float4 v0 = *(const float4*)(img_b + p0);
        float4 v1 = *(const float4*)(img_b + p0 + HW);
        float4 v2 = *(const float4*)(img_b + p0 + 2 * HW);

        red_add_v4(pool_rb + s.x * ROW_F4, v0.x, v1.x, v2.x);
        red_add_v4(pool_rb + s.y * ROW_F4, v0.y, v1.y, v2.y);
        red_add_v4(pool_rb + s.z * ROW_F4, v0.z, v1.z, v2.z);
        red_add_v4(pool_rb + s.w * ROW_F4, v0.w, v1.w, v2.w);
    }

    // Prefetch phase-2 operands (independent of the barrier)
    float w0c[COLS_PER_THREAD], w1c[COLS_PER_THREAD], w2c[COLS_PER_THREAD];
    float bbc[COLS_PER_THREAD];
#pragma unroll
    for (int jj = 0; jj < COLS_PER_THREAD; jj++) {
        int e = tid + jj * TA;
        w0c[jj] = Wmat[0 * Ex + e];
        w1c[jj] = Wmat[1 * Ex + e];
        w2c[jj] = Wmat[2 * Ex + e];
        bbc[jj] = bias[e];
    }

    // ---------------- Per-batch sub-barrier (74 arrivals; proven form) ------
    __threadfence();                       // REDs globally visible first
    __syncthreads();                       // all warps' REDs issued
    if (tid == 0) {
        unsigned long long* bar = &g_bar[b * 16];
        unsigned long long old = atomicAdd(bar, 1ULL);
        unsigned long long target = (old / BPB + 1ULL) * BPB;
        while (*(volatile unsigned long long*)bar < target) { }
    }
    __syncthreads();
    // Phase-2 pooled reads use ld.global.cg (L2 is the coherence point).

    // ---------------- Phase 2: rows j, j+74, j+148 of this batch ------------
    const float inv = 1.0f / (float)HW;

    float p0a[MAXROWS], p1a[MAXROWS], p2a[MAXROWS];
#pragma unroll
    for (int i = 0; i < MAXROWS; i++) {
        int r = j + BPB * i;
        p0a[i] = p1a[i] = p2a[i] = 0.f;
        if (r < Kx) {
#pragma unroll
            for (int rp = 0; rp < NREP; rp++) {
                float4 q = ldcg4(&g_pool4[((size_t)rp * BK + b * Kx + r) * ROW_F4]);
                p0a[i] += q.x; p1a[i] += q.y; p2a[i] += q.z;
            }
        }
    }

#pragma unroll
    for (int i = 0; i < MAXROWS; i++) {
        int r = j + BPB * i;
        if (r < Kx) {
            const int bk = b * Kx + r;
            float p0 = p0a[i] * inv, p1 = p1a[i] * inv, p2 = p2a[i] * inv;
#pragma unroll
            for (int jj = 0; jj < COLS_PER_THREAD; jj++) {
                int e = tid + jj * TA;
                float acc = bbc[jj];
                acc = fmaf(p0, w0c[jj], acc);
                acc = fmaf(p1, w1c[jj], acc);
                acc = fmaf(p2, w2c[jj], acc);
                out[(size_t)bk * Ex + e] = acc;
            }
        }
    }

    // Restore the zero-invariant for all replicas of the rows this block read.
    __syncthreads();
    if (tid < MAXROWS * NREP) {
        const int i  = tid >> 3;           // 0..2
        const int rp = tid & 7;
        const int r  = j + BPB * i;
        if (r < Kx) {
            g_pool4[((size_t)rp * BK + b * Kx + r) * ROW_F4] =
                make_float4(0.f, 0.f, 0.f, 0.f);
        }
    }
}

extern "C" void kernel_launch(void* const* d_in, const int* in_sizes, int n_in,
                              void* d_out, int out_size) {
    const float* img  = (const float*)d_in[0];
    const int*   seg  = (const int*)d_in[1];
    const float* Wmat = (const float*)d_in[2];
    const float* bias = (const float*)d_in[3];
    float* out = (float*)d_out;

    fused_kernel<<<NBLK, TA>>>(img, seg, Wmat, bias, out);
}

// round 16
// speedup vs baseline: 1.1633x; 1.1633x over previous
#include <cuda_runtime.h>
#include <cuda_bf16.h>

// Problem constants
#define Bx 4
#define Cx 3
#define Hx 224
#define Wx 224
#define Kx 196
#define Ex 768
#define HW (Hx * Wx)               // 50176
#define KC (Kx * Cx)               // 588
#define BK (Bx * Kx)               // 784

#define BPB 49                     // blocks per batch (R10 proven grid)
#define NBLK (Bx * BPB)            // 196
#define TA 256
#define PIX_PER_BLOCK (TA * 4)     // 1024; 49*1024 = HW exactly

#define ROWS_PER_BLOCK 4           // 49 blocks * 4 rows = 196 = Kx
#define COLS_PER_THREAD (Ex / TA)  // 3
#define ROW_F4 8                   // 128 B per (b,k) row (L2-slice spread)

// Pooled sums; element 0 of each row = {c0,c1,c2,pad}. Zero at module load;
// phase 2 re-zeroes consumed rows, so the zero-invariant holds every call.
__device__ float4 g_pool4[BK * ROW_F4];

// Per-batch sub-barriers: monotone epoch counters, 128 B apart. u64 -> no overflow.
__device__ unsigned long long g_bar[Bx * 16];

__device__ __forceinline__ void red_add_v4(float4* p, float x, float y, float z) {
    asm volatile("red.global.add.v4.f32 [%0], {%1, %2, %3, %4};"
                 :: "l"(p), "f"(x), "f"(y), "f"(z), "f"(0.0f) : "memory");
}

__device__ __forceinline__ float4 ldcg4(const float4* p) {
    float4 v;
    asm volatile("ld.global.cg.v4.f32 {%0,%1,%2,%3}, [%4];"
                 : "=f"(v.x), "=f"(v.y), "=f"(v.z), "=f"(v.w) : "l"(p));
    return v;
}

__global__ void __launch_bounds__(TA)
fused_kernel(const float* __restrict__ img,
             const int* __restrict__ seg,
             const float* __restrict__ Wmat,
             const float* __restrict__ bias,
             float* __restrict__ out) {
    __shared__ float s_pool[KC];

    const int tid = threadIdx.x;
    const int b   = blockIdx.x / BPB;
    const int j   = blockIdx.x % BPB;

    // ---------------- Phase 1: segment-sum ----------------
    // Issue the 4 independent global loads FIRST so their L2/DRAM latency
    // overlaps the shared-pool zeroing below.
    const int p0 = j * PIX_PER_BLOCK + tid * 4;
    const float* img_b = img + (size_t)b * Cx * HW;
    const int*   seg_b = seg + (size_t)b * HW;

    int4   s  = *(const int4*)  (seg_b + p0);
    float4 v0 = *(const float4*)(img_b + p0);
    float4 v1 = *(const float4*)(img_b + p0 + HW);
    float4 v2 = *(const float4*)(img_b + p0 + 2 * HW);

    for (int i = tid; i < KC; i += TA) s_pool[i] = 0.0f;
    __syncthreads();

    atomicAdd(&s_pool[s.x * Cx + 0], v0.x);
    atomicAdd(&s_pool[s.x * Cx + 1], v1.x);
    atomicAdd(&s_pool[s.x * Cx + 2], v2.x);
    atomicAdd(&s_pool[s.y * Cx + 0], v0.y);
    atomicAdd(&s_pool[s.y * Cx + 1], v1.y);
    atomicAdd(&s_pool[s.y * Cx + 2], v2.y);
    atomicAdd(&s_pool[s.z * Cx + 0], v0.z);
    atomicAdd(&s_pool[s.z * Cx + 1], v1.z);
    atomicAdd(&s_pool[s.z * Cx + 2], v2.z);
    atomicAdd(&s_pool[s.w * Cx + 0], v0.w);
    atomicAdd(&s_pool[s.w * Cx + 1], v1.w);
    atomicAdd(&s_pool[s.w * Cx + 2], v2.w);

    __syncthreads();

    // Flush: one fire-and-forget vector RED per key (distinct addresses
    // within a block -> pure issue cost).
    if (tid < Kx) {
        float c0 = s_pool[tid * Cx + 0];
        float c1 = s_pool[tid * Cx + 1];
        float c2 = s_pool[tid * Cx + 2];
        red_add_v4(&g_pool4[(b * Kx + tid) * ROW_F4], c0, c1, c2);
    }

    // Prefetch phase-2 operands (independent of the barrier)
    float w0c[COLS_PER_THREAD], w1c[COLS_PER_THREAD], w2c[COLS_PER_THREAD];
    float bbc[COLS_PER_THREAD];
#pragma unroll
    for (int jj = 0; jj < COLS_PER_THREAD; jj++) {
        int e = tid + jj * TA;
        w0c[jj] = Wmat[0 * Ex + e];
        w1c[jj] = Wmat[1 * Ex + e];
        w2c[jj] = Wmat[2 * Ex + e];
        bbc[jj] = bias[e];
    }

    // ---------------- Per-batch sub-barrier (49 arrivals) ----------------
    // syncthreads BEFORE the fence/arrival: guarantees every warp's flush
    // RED has been issued before tid0 signals this block's arrival
    // (fixes a warp-skew race present in earlier rounds).
    __syncthreads();
    __threadfence();                       // REDs globally visible first
    if (tid == 0) {
        unsigned long long* bar = &g_bar[b * 16];
        unsigned long long old = atomicAdd(bar, 1ULL);
        unsigned long long target = (old / BPB + 1ULL) * BPB;
        while (*(volatile unsigned long long*)bar < target) { }
    }
    __syncthreads();
    // Phase-2 pooled reads use ld.global.cg (L2 is the coherence point).

    // ---------------- Phase 2: 4 rows of this block's own batch ----------
    const float inv = 1.0f / (float)HW;
    const int bk0 = b * Kx + j * ROWS_PER_BLOCK;

    // Issue all 4 row loads up front (independent -> one L2 round-trip)
    float4 q[ROWS_PER_BLOCK];
#pragma unroll
    for (int r = 0; r < ROWS_PER_BLOCK; r++) {
        q[r] = ldcg4(&g_pool4[(bk0 + r) * ROW_F4]);
    }

#pragma unroll
    for (int r = 0; r < ROWS_PER_BLOCK; r++) {
        const int bk = bk0 + r;
        float p0 = q[r].x * inv, p1 = q[r].y * inv, p2 = q[r].z * inv;
#pragma unroll
        for (int jj = 0; jj < COLS_PER_THREAD; jj++) {
            int e = tid + jj * TA;
            float acc = bbc[jj];
            acc = fmaf(p0, w0c[jj], acc);
            acc = fmaf(p1, w1c[jj], acc);
            acc = fmaf(p2, w2c[jj], acc);
            out[(size_t)bk * Ex + e] = acc;
        }
    }

    // Restore the zero-invariant for the rows this block consumed.
    __syncthreads();
    if (tid < ROWS_PER_BLOCK) {
        g_pool4[(bk0 + tid) * ROW_F4] = make_float4(0.f, 0.f, 0.f, 0.f);
    }
}

extern "C" void kernel_launch(void* const* d_in, const int* in_sizes, int n_in,
                              void* d_out, int out_size) {
    const float* img  = (const float*)d_in[0];
    const int*   seg  = (const int*)d_in[1];
    const float* Wmat = (const float*)d_in[2];
    const float* bias = (const float*)d_in[3];
    float* out = (float*)d_out;

    fused_kernel<<<NBLK, TA>>>(img, seg, Wmat, bias, out);
}

// round 17
// speedup vs baseline: 1.4615x; 1.2564x over previous
#include <cuda_runtime.h>
#include <cuda_bf16.h>

// Problem constants
#define Bx 4
#define Cx 3
#define Hx 224
#define Wx 224
#define Kx 196
#define Ex 768
#define HW (Hx * Wx)               // 50176
#define KC (Kx * Cx)               // 588
#define BK (Bx * Kx)               // 784

#define BPB 49                     // blocks per batch (proven grid)
#define NBLK (Bx * BPB)            // 196
#define TA 256
#define PIX_PER_BLOCK (TA * 4)     // 1024; 49*1024 = HW exactly

#define ROWS_PER_BLOCK 4           // 49 blocks * 4 rows = 196 = Kx
#define COLS_PER_THREAD (Ex / TA)  // 3
#define ROW_F4 8                   // 128 B per (b,k) row (L2-slice spread)

// Pooled sums; element 0 of each row = {c0,c1,c2,pad}. Zero at module load;
// phase 2 re-zeroes consumed rows, so the zero-invariant holds every call.
__device__ float4 g_pool4[BK * ROW_F4];

// Per-batch sub-barriers: monotone epoch counters, 128 B apart. u64 -> no overflow.
__device__ unsigned long long g_bar[Bx * 16];

__device__ __forceinline__ void red_add_v4(float4* p, float x, float y, float z) {
    asm volatile("red.global.add.v4.f32 [%0], {%1, %2, %3, %4};"
                 :: "l"(p), "f"(x), "f"(y), "f"(z), "f"(0.0f) : "memory");
}

__device__ __forceinline__ float4 ldcg4(const float4* p) {
    float4 v;
    asm volatile("ld.global.cg.v4.f32 {%0,%1,%2,%3}, [%4];"
                 : "=f"(v.x), "=f"(v.y), "=f"(v.z), "=f"(v.w) : "l"(p));
    return v;
}

__global__ void __launch_bounds__(TA)
fused_kernel(const float* __restrict__ img,
             const int* __restrict__ seg,
             const float* __restrict__ Wmat,
             const float* __restrict__ bias,
             float* __restrict__ out) {
    __shared__ float s_pool[KC];

    const int tid = threadIdx.x;
    const int b   = blockIdx.x / BPB;
    const int j   = blockIdx.x % BPB;

    // ---------------- Phase 1: segment-sum ----------------
    // Issue the 4 independent global loads FIRST so their L2/DRAM latency
    // overlaps the shared-pool zeroing below.
    const int p0 = j * PIX_PER_BLOCK + tid * 4;
    const float* img_b = img + (size_t)b * Cx * HW;
    const int*   seg_b = seg + (size_t)b * HW;

    int4   s  = *(const int4*)  (seg_b + p0);
    float4 v0 = *(const float4*)(img_b + p0);
    float4 v1 = *(const float4*)(img_b + p0 + HW);
    float4 v2 = *(const float4*)(img_b + p0 + 2 * HW);

    for (int i = tid; i < KC; i += TA) s_pool[i] = 0.0f;
    __syncthreads();

    atomicAdd(&s_pool[s.x * Cx + 0], v0.x);
    atomicAdd(&s_pool[s.x * Cx + 1], v1.x);
    atomicAdd(&s_pool[s.x * Cx + 2], v2.x);
    atomicAdd(&s_pool[s.y * Cx + 0], v0.y);
    atomicAdd(&s_pool[s.y * Cx + 1], v1.y);
    atomicAdd(&s_pool[s.y * Cx + 2], v2.y);
    atomicAdd(&s_pool[s.z * Cx + 0], v0.z);
    atomicAdd(&s_pool[s.z * Cx + 1], v1.z);
    atomicAdd(&s_pool[s.z * Cx + 2], v2.z);
    atomicAdd(&s_pool[s.w * Cx + 0], v0.w);
    atomicAdd(&s_pool[s.w * Cx + 1], v1.w);
    atomicAdd(&s_pool[s.w * Cx + 2], v2.w);

    __syncthreads();

    // Flush: one fire-and-forget vector RED per key.
    if (tid < Kx) {
        float c0 = s_pool[tid * Cx + 0];
        float c1 = s_pool[tid * Cx + 1];
        float c2 = s_pool[tid * Cx + 2];
        red_add_v4(&g_pool4[(b * Kx + tid) * ROW_F4], c0, c1, c2);
    }

    // Prefetch phase-2 operands (independent of the barrier)
    float w0c[COLS_PER_THREAD], w1c[COLS_PER_THREAD], w2c[COLS_PER_THREAD];
    float bbc[COLS_PER_THREAD];
#pragma unroll
    for (int jj = 0; jj < COLS_PER_THREAD; jj++) {
        int e = tid + jj * TA;
        w0c[jj] = Wmat[0 * Ex + e];
        w1c[jj] = Wmat[1 * Ex + e];
        w2c[jj] = Wmat[2 * Ex + e];
        bbc[jj] = bias[e];
    }

    // ---------------- Per-batch sub-barrier (49 arrivals) ----------------
    // syncthreads first: every warp's flush RED is issued before tid0 arrives.
    // The RELEASE on the arrival atomic orders this block's prior global REDs
    // at L2 without an SM-side full-membar drain (replaces __threadfence()).
    __syncthreads();
    if (tid == 0) {
        unsigned long long* bar = &g_bar[b * 16];
        unsigned long long old;
        asm volatile("atom.release.gpu.global.add.u64 %0, [%1], %2;"
                     : "=l"(old) : "l"(bar), "l"(1ULL) : "memory");
        unsigned long long target = (old / BPB + 1ULL) * BPB;
        unsigned long long cur;
        do {
            asm volatile("ld.acquire.gpu.global.u64 %0, [%1];"
                         : "=l"(cur) : "l"(bar) : "memory");
        } while (cur < target);
    }
    __syncthreads();
    // Acquire on the spin load + ld.global.cg reads (L2 coherence point).

    // ---------------- Phase 2: 4 rows of this block's own batch ----------
    const float inv = 1.0f / (float)HW;
    const int bk0 = b * Kx + j * ROWS_PER_BLOCK;

    // Issue all 4 row loads up front (independent -> one L2 round-trip)
    float4 q[ROWS_PER_BLOCK];
#pragma unroll
    for (int r = 0; r < ROWS_PER_BLOCK; r++) {
        q[r] = ldcg4(&g_pool4[(bk0 + r) * ROW_F4]);
    }

#pragma unroll
    for (int r = 0; r < ROWS_PER_BLOCK; r++) {
        const int bk = bk0 + r;
        float p0 = q[r].x * inv, p1 = q[r].y * inv, p2 = q[r].z * inv;
#pragma unroll
        for (int jj = 0; jj < COLS_PER_THREAD; jj++) {
            int e = tid + jj * TA;
            float acc = bbc[jj];
            acc = fmaf(p0, w0c[jj], acc);
            acc = fmaf(p1, w1c[jj], acc);
            acc = fmaf(p2, w2c[jj], acc);
            out[(size_t)bk * Ex + e] = acc;
        }
    }

    // Restore the zero-invariant for the rows this block consumed.
    __syncthreads();
    if (tid < ROWS_PER_BLOCK) {
        g_pool4[(bk0 + tid) * ROW_F4] = make_float4(0.f, 0.f, 0.f, 0.f);
    }
}

extern "C" void kernel_launch(void* const* d_in, const int* in_sizes, int n_in,
                              void* d_out, int out_size) {
    const float* img  = (const float*)d_in[0];
    const int*   seg  = (const int*)d_in[1];
    const float* Wmat = (const float*)d_in[2];
    const float* bias = (const float*)d_in[3];
    float* out = (float*)d_out;

    fused_kernel<<<NBLK, TA>>>(img, seg, Wmat, bias, out);
}